// round 5
// baseline (speedup 1.0000x reference)
#include <cuda_runtime.h>
#include <cuda_fp16.h>
#include <stdint.h>

// ---------------------------------------------------------------------------
// Problem constants
// ---------------------------------------------------------------------------
#define N_TOK 65536
#define DIM   1024
#define S_SEM 200
#define NPACK 352      // 1 cls + 12 fused-sem + 324 bbox + 15 zero pad
#define NSC   81
#define NBB   324
#define BM    128
#define BK    64
#define NKCH  (DIM / BK)     // 16
#define THREADS 512

// Packed fp16 weights + fp32 bias (built by prep kernel every launch)
__device__ __half g_Wp[NPACK * DIM];
__device__ float  g_bp[NPACK];

// Selected class indices (0-based into the 80 class cols): {i-1 : i in IGNORE2} U {79}
__constant__ int c_sel[12] = {1, 2, 16, 18, 29, 37, 47, 53, 63, 68, 72, 79};

__device__ __forceinline__ constexpr bool cls_keep(int j) {
    return j == 1 || j == 2 || j == 16 || j == 18 || j == 29 || j == 37 ||
           j == 47 || j == 53 || j == 63 || j == 68 || j == 72 || j == 79;
}

__device__ __forceinline__ uint32_t smem_u32(const void* p) {
    uint32_t a;
    asm("{ .reg .u64 t; cvta.to.shared.u64 t, %1; cvt.u32.u64 %0, t; }"
        : "=r"(a) : "l"(p));
    return a;
}

// ---------------------------------------------------------------------------
// SMEM layout (bytes)
// ---------------------------------------------------------------------------
#define SMO_BIAS 0                              // 352 f32 (+pad) = 1536
#define SMO_A16  1536                           // 2 x 128 x 128B = 32768
#define SMO_B    (SMO_A16 + 2 * BM * 128)       // 34304; 3 x 352 x 128B = 135168
#define SM_TOTAL (SMO_B + 3 * NPACK * 128)      // 169472

// ---------------------------------------------------------------------------
// Prep: pack [W_cls ; sem_matrix[sel] @ W_sem / S ; W_bbox ; 0-pad] -> fp16
// Blocks 0..47: sem fusion (12 rows x 4 d-chunks of 256). Blocks 48..399: copies.
// ---------------------------------------------------------------------------
#define SEM_BLKS 48
__global__ void prep_kernel(const float* __restrict__ W_cls,
                            const float* __restrict__ b_cls,
                            const float* __restrict__ W_sem,
                            const float* __restrict__ b_sem,
                            const float* __restrict__ W_bbox,
                            const float* __restrict__ b_bbox,
                            const float* __restrict__ sem_m) {
    const int tid = threadIdx.x;
    const int bid = blockIdx.x;
    if (bid < SEM_BLKS) {
        __shared__ float sM[S_SEM];
        const int r = (bid >> 2) + 1;            // packed row 1..12
        const int chunk = bid & 3;
        const int sj = c_sel[r - 1];
        const float* M = sem_m + (size_t)sj * S_SEM;
        if (tid < S_SEM) sM[tid] = M[tid];
        __syncthreads();
        const int d = chunk * 256 + tid;
        const float* Wcol = W_sem + d;
        float a0 = 0.f, a1 = 0.f, a2 = 0.f, a3 = 0.f;
#pragma unroll 4
        for (int s = 0; s < S_SEM; s += 4) {
            a0 += sM[s + 0] * Wcol[(size_t)(s + 0) * DIM];
            a1 += sM[s + 1] * Wcol[(size_t)(s + 1) * DIM];
            a2 += sM[s + 2] * Wcol[(size_t)(s + 2) * DIM];
            a3 += sM[s + 3] * Wcol[(size_t)(s + 3) * DIM];
        }
        g_Wp[(size_t)r * DIM + d] = __float2half(((a0 + a1) + (a2 + a3)) * (1.0f / S_SEM));
        if (chunk == 0 && tid < 32) {
            float p = 0.f;
            for (int s = tid; s < S_SEM; s += 32) p += sM[s] * b_sem[s];
#pragma unroll
            for (int o = 16; o > 0; o >>= 1) p += __shfl_xor_sync(0xffffffffu, p, o);
            if (tid == 0) g_bp[r] = p * (1.0f / S_SEM);
        }
    } else {
        const int r = bid - SEM_BLKS;            // 0..351
        if (r >= 1 && r <= 12) return;           // sem blocks own these
        __half* dst = g_Wp + (size_t)r * DIM;
        if (r == 0) {
            float4 v = ((const float4*)W_cls)[tid];
            ((__half2*)dst)[tid * 2 + 0] = __floats2half2_rn(v.x, v.y);
            ((__half2*)dst)[tid * 2 + 1] = __floats2half2_rn(v.z, v.w);
            if (tid == 0) g_bp[0] = b_cls[0];
        } else if (r < 13 + NBB) {
            const int c = r - 13;
            float4 v = ((const float4*)(W_bbox + (size_t)c * DIM))[tid];
            ((__half2*)dst)[tid * 2 + 0] = __floats2half2_rn(v.x, v.y);
            ((__half2*)dst)[tid * 2 + 1] = __floats2half2_rn(v.z, v.w);
            if (tid == 0) g_bp[r] = b_bbox[c];
        } else {
            ((__half2*)dst)[tid * 2 + 0] = __floats2half2_rn(0.f, 0.f);
            ((__half2*)dst)[tid * 2 + 1] = __floats2half2_rn(0.f, 0.f);
            if (tid == 0) g_bp[r] = 0.0f;
        }
    }
}

// ---------------------------------------------------------------------------
// Main GEMM: [128, 1024] x [1024, 352] per CTA via mma.sync m16n8k16 fp16
// A: LDG fp32 prefetch (regs) -> cvt -> STS fp16 (double buffer)
// B: cp.async fp16, 3-stage pipeline
// ---------------------------------------------------------------------------
__global__ void __launch_bounds__(THREADS, 1)
fpn_gemm(const float* __restrict__ x, float* __restrict__ out) {
    extern __shared__ char smem[];
    float* s_bias = (float*)(smem + SMO_BIAS);
    const uint32_t sbA16 = smem_u32(smem + SMO_A16);
    const uint32_t sbB   = smem_u32(smem + SMO_B);

    const int tid = threadIdx.x;
    const int wid = tid >> 5, lid = tid & 31;
    const int wm = wid >> 2, wn = wid & 3;        // 4 warps M x 4 warps N
    const int mbase = blockIdx.x * BM;
    const int q = lid >> 2, t = lid & 3;

    for (int i = tid; i < NPACK; i += THREADS) s_bias[i] = g_bp[i];

    float acc[2][11][4];
#pragma unroll
    for (int a = 0; a < 2; a++)
#pragma unroll
        for (int b = 0; b < 11; b++)
#pragma unroll
            for (int e = 0; e < 4; e++) acc[a][b][e] = 0.0f;

    // A prefetch registers: 4 x float4 per thread (one 128x64-f32 chunk / CTA)
    float4 areg[4];
    const int a_r = tid >> 4;            // row 0..127 (rows 0..31 for it=0, +32/it)
    const int a_j = tid & 15;            // 16B unit within 64-float row

    auto ldgA = [&](int kc) {
        const float4* xs = (const float4*)(x + (size_t)mbase * DIM + kc * BK);
#pragma unroll
        for (int it = 0; it < 4; it++) {
            int r = a_r + it * 32;
            areg[it] = __ldg(xs + (size_t)r * (DIM / 4) + a_j);
        }
    };
    auto stsA = [&](int kc) {
        char* adst = smem + SMO_A16 + (kc & 1) * (BM * 128);
#pragma unroll
        for (int it = 0; it < 4; it++) {
            int r = a_r + it * 32;
            union { __half2 h[2]; uint2 u; } p;
            p.h[0] = __floats2half2_rn(areg[it].x, areg[it].y);
            p.h[1] = __floats2half2_rn(areg[it].z, areg[it].w);
            uint32_t off = (uint32_t)(r * 128 + a_j * 8);
            *(uint2*)(adst + (off ^ ((off >> 3) & 0x70))) = p.u;
        }
    };
    auto stageB = [&](int kc) {
        if (kc < NKCH) {
            const char* ws = (const char*)g_Wp + (size_t)kc * (BK * 2);
            const uint32_t bdst = sbB + (kc % 3) * (NPACK * 128);
#pragma unroll
            for (int it = 0; it < 6; it++) {
                int i = it * THREADS + tid;
                if (it < 5 || i < NPACK * 8) {
                    int r = i >> 3, j = i & 7;
                    uint32_t off = (uint32_t)(r * 128 + j * 16);
                    uint32_t d = bdst + (off ^ ((off >> 3) & 0x70));
                    const char* s = ws + (size_t)r * (DIM * 2) + j * 16;
                    asm volatile("cp.async.cg.shared.global [%0], [%1], 16;"
                                 :: "r"(d), "l"(s));
                }
            }
        }
        asm volatile("cp.async.commit_group;" ::: "memory");
    };

    // Prologue
    ldgA(0);
    stageB(0);
    stageB(1);

    for (int kc = 0; kc < NKCH; kc++) {
        stsA(kc);                            // cvt regs -> A16 buf kc&1
        if (kc + 1 < NKCH) ldgA(kc + 1);     // prefetch next A chunk
        asm volatile("cp.async.wait_group 1;" ::: "memory");   // B(kc) ready
        __syncthreads();                     // A16 + B visible; guards reuse
        stageB(kc + 2);                      // overlap next-next B with MMA

        const uint32_t Abuf = sbA16 + (kc & 1) * (BM * 128);
        const uint32_t Bbuf = sbB + (kc % 3) * (NPACK * 128);

#pragma unroll
        for (int ks = 0; ks < 4; ks++) {
            // ---- A fragments via ldmatrix.x4 ----
            uint32_t af[2][4];
#pragma unroll
            for (int mf = 0; mf < 2; mf++) {
                uint32_t row = (uint32_t)(wm * 32 + mf * 16 + (lid & 15));
                uint32_t off = row * 128 + (uint32_t)(ks * 32 + ((lid >> 4) & 1) * 16);
                uint32_t addr = Abuf + (off ^ ((off >> 3) & 0x70));
                asm volatile("ldmatrix.sync.aligned.m8n8.x4.shared.b16 {%0,%1,%2,%3}, [%4];"
                             : "=r"(af[mf][0]), "=r"(af[mf][1]),
                               "=r"(af[mf][2]), "=r"(af[mf][3]) : "r"(addr));
            }
            // ---- B fragments: x4 covers two n-frags (both k halves) ----
#pragma unroll
            for (int np = 0; np < 5; np++) {
                const int nf = np * 2;
                // lanes 0-7: nf rows k-lo | 8-15: nf rows k-hi
                // lanes 16-23: nf+1 rows k-lo | 24-31: nf+1 rows k-hi
                int row = wn * 88 + (nf + ((lid >> 4) & 1)) * 8 + (lid & 7);
                uint32_t off = (uint32_t)(row * 128 + ks * 32 + ((lid >> 3) & 1) * 16);
                uint32_t addr = Bbuf + (off ^ ((off >> 3) & 0x70));
                uint32_t b0, b1, b2, b3;
                asm volatile("ldmatrix.sync.aligned.m8n8.x4.shared.b16 {%0,%1,%2,%3}, [%4];"
                             : "=r"(b0), "=r"(b1), "=r"(b2), "=r"(b3) : "r"(addr));
#pragma unroll
                for (int mf = 0; mf < 2; mf++) {
                    asm volatile(
                        "mma.sync.aligned.m16n8k16.row.col.f32.f16.f16.f32 "
                        "{%0,%1,%2,%3},{%4,%5,%6,%7},{%8,%9},{%0,%1,%2,%3};"
                        : "+f"(acc[mf][nf][0]), "+f"(acc[mf][nf][1]),
                          "+f"(acc[mf][nf][2]), "+f"(acc[mf][nf][3])
                        : "r"(af[mf][0]), "r"(af[mf][1]), "r"(af[mf][2]), "r"(af[mf][3]),
                          "r"(b0), "r"(b1));
                    asm volatile(
                        "mma.sync.aligned.m16n8k16.row.col.f32.f16.f16.f32 "
                        "{%0,%1,%2,%3},{%4,%5,%6,%7},{%8,%9},{%0,%1,%2,%3};"
                        : "+f"(acc[mf][nf + 1][0]), "+f"(acc[mf][nf + 1][1]),
                          "+f"(acc[mf][nf + 1][2]), "+f"(acc[mf][nf + 1][3])
                        : "r"(af[mf][0]), "r"(af[mf][1]), "r"(af[mf][2]), "r"(af[mf][3]),
                          "r"(b2), "r"(b3));
                }
            }
            {   // ---- last n-frag (nf = 10), x2 ----
                const int nf = 10;
                int row = wn * 88 + nf * 8 + (lid & 7);
                uint32_t off = (uint32_t)(row * 128 + ks * 32 + ((lid >> 3) & 1) * 16);
                uint32_t addr = Bbuf + (off ^ ((off >> 3) & 0x70));
                uint32_t b0, b1;
                asm volatile("ldmatrix.sync.aligned.m8n8.x2.shared.b16 {%0,%1}, [%2];"
                             : "=r"(b0), "=r"(b1) : "r"(addr));
#pragma unroll
                for (int mf = 0; mf < 2; mf++) {
                    asm volatile(
                        "mma.sync.aligned.m16n8k16.row.col.f32.f16.f16.f32 "
                        "{%0,%1,%2,%3},{%4,%5,%6,%7},{%8,%9},{%0,%1,%2,%3};"
                        : "+f"(acc[mf][nf][0]), "+f"(acc[mf][nf][1]),
                          "+f"(acc[mf][nf][2]), "+f"(acc[mf][nf][3])
                        : "r"(af[mf][0]), "r"(af[mf][1]), "r"(af[mf][2]), "r"(af[mf][3]),
                          "r"(b0), "r"(b1));
                }
            }
        }
    }

    // ---- zero the 68 masked class-score columns ----
    {
        int r = tid >> 2, sub = tid & 3;
        float* srow = out + (size_t)(mbase + r) * NSC;
#pragma unroll
        for (int j = sub; j < 80; j += 4)
            if (!cls_keep(j)) srow[1 + j] = 0.0f;
    }

    // ---- scatter accumulators (+bias) ----
#pragma unroll
    for (int mf = 0; mf < 2; mf++) {
#pragma unroll
        for (int half = 0; half < 2; half++) {
            const int m = mbase + wm * 32 + mf * 16 + q + half * 8;
            float* srow = out + (size_t)m * NSC;
            float* brow = out + (size_t)N_TOK * NSC + (size_t)m * NBB;
#pragma unroll
            for (int nf = 0; nf < 11; nf++) {
#pragma unroll
                for (int e = 0; e < 2; e++) {
                    const int c = wn * 88 + nf * 8 + t * 2 + e;
                    float v = acc[mf][nf][half * 2 + e] + s_bias[c];
                    if (c == 0)        srow[0] = v;
                    else if (c <= 12)  srow[1 + c_sel[c - 1]] = v;
                    else if (c <= 336) brow[c - 13] = v;
                }
            }
        }
    }
}

// ---------------------------------------------------------------------------
// Launch
// ---------------------------------------------------------------------------
extern "C" void kernel_launch(void* const* d_in, const int* in_sizes, int n_in,
                              void* d_out, int out_size) {
    const float* x      = (const float*)d_in[0];
    const float* W_cls  = (const float*)d_in[1];
    const float* b_cls  = (const float*)d_in[2];
    const float* W_sem  = (const float*)d_in[3];
    const float* b_sem  = (const float*)d_in[4];
    const float* W_bbox = (const float*)d_in[5];
    const float* b_bbox = (const float*)d_in[6];
    const float* sem_m  = (const float*)d_in[7];
    float* out = (float*)d_out;

    cudaFuncSetAttribute(fpn_gemm, cudaFuncAttributeMaxDynamicSharedMemorySize, SM_TOTAL);

    prep_kernel<<<SEM_BLKS + NPACK, 256>>>(W_cls, b_cls, W_sem, b_sem, W_bbox, b_bbox, sem_m);
    fpn_gemm<<<N_TOK / BM, THREADS, SM_TOTAL>>>(x, out);
}